// round 2
// baseline (speedup 1.0000x reference)
#include <cuda_runtime.h>
#include <cuda_bf16.h>

#define Bsz  512
#define Ssz  1024
#define Esz  48
#define Hsz  128
#define NCLS 2000
#define BC   4      // batch rows per CTA
#define KC   44     // k-slices of w_hh cached in smem (rest streams from L2)

// Packed parameter storage (prepared once per launch by prep_kernel).
// g_wPack  : [gp][k][j][gi]   gp=gate-pair (0:i,f  1:g,o), gi in {0,1}
// g_wIhPack: [gp][e][j][gi]
// g_bias   : [gp][j][gi]      (= b_ih + b_hh)
// g_wfcT   : [k][n]
__device__ float g_wPack  [2 * Hsz * Hsz * 2];
__device__ float g_wIhPack[2 * Esz * Hsz * 2];
__device__ float g_bias   [2 * Hsz * 2];
__device__ float g_wfcT   [Hsz * NCLS];
__device__ float g_hfin   [Bsz * Hsz];

__device__ __forceinline__ float sigf(float x) { return 1.0f / (1.0f + expf(-x)); }

// ---------------------------------------------------------------------------
// Prep: transpose/pack weights (idempotent, runs every launch).
// ---------------------------------------------------------------------------
__global__ void prep_kernel(const float* __restrict__ w_ih, const float* __restrict__ w_hh,
                            const float* __restrict__ b_ih, const float* __restrict__ b_hh,
                            const float* __restrict__ w_fc) {
    int i = blockIdx.x * blockDim.x + threadIdx.x;
    if (i < 2 * Hsz * Hsz * 2) {
        int gi = i & 1, j = (i >> 1) & 127, k = (i >> 8) & 127, gp = i >> 15;
        g_wPack[i] = w_hh[((gp * 2 + gi) * Hsz + j) * Hsz + k];
    }
    if (i < 2 * Esz * Hsz * 2) {
        int gi = i & 1, j = (i >> 1) & 127;
        int t = i >> 8;
        int e = t % Esz, gp = t / Esz;
        g_wIhPack[i] = w_ih[((gp * 2 + gi) * Hsz + j) * Esz + e];
    }
    if (i < 2 * Hsz * 2) {
        int gi = i & 1, j = (i >> 1) & 127, gp = i >> 8;
        int r = (gp * 2 + gi) * Hsz + j;
        g_bias[i] = b_ih[r] + b_hh[r];
    }
    if (i < Hsz * NCLS) {
        int k = i / NCLS, n = i % NCLS;
        g_wfcT[i] = w_fc[n * Hsz + k];
    }
}

// ---------------------------------------------------------------------------
// LSTM recurrence: persistent CTA over all 1024 steps for BC=4 batch rows.
// tid = gp*128 + j : thread computes 2 gate rows (gi=0,1) x 4 batches.
// ---------------------------------------------------------------------------
struct alignas(16) Smem {
    float wih[2 * Esz * Hsz * 2];   // 24576 f  (full w_ih, packed)
    float whh[2 * KC  * Hsz * 2];   // 22528 f  (k < KC slice of w_hh)
    float h[BC][Hsz];
    float c[BC][Hsz];
    float gbuf[4][BC][Hsz];         // gate order i,f,g,o
    float e[2][BC][Esz];            // double-buffered embeddings
    int   tok[BC][Ssz];
};

#define FMA8(W2, H0, H1, H2, H3)                                      \
    do {                                                              \
        a00 = fmaf((W2).x, (H0), a00); a01 = fmaf((W2).x, (H1), a01); \
        a02 = fmaf((W2).x, (H2), a02); a03 = fmaf((W2).x, (H3), a03); \
        a10 = fmaf((W2).y, (H0), a10); a11 = fmaf((W2).y, (H1), a11); \
        a12 = fmaf((W2).y, (H2), a12); a13 = fmaf((W2).y, (H3), a13); \
    } while (0)

#define KBODY(WPTR, KK)                                               \
    do {                                                              \
        const float4 hv0 = *(const float4*)(&s->h[0][(KK) * 4]);      \
        const float4 hv1 = *(const float4*)(&s->h[1][(KK) * 4]);      \
        const float4 hv2 = *(const float4*)(&s->h[2][(KK) * 4]);      \
        const float4 hv3 = *(const float4*)(&s->h[3][(KK) * 4]);      \
        const float2 w0 = *(const float2*)((WPTR) + 0 * 256);         \
        const float2 w1 = *(const float2*)((WPTR) + 1 * 256);         \
        const float2 w2 = *(const float2*)((WPTR) + 2 * 256);         \
        const float2 w3 = *(const float2*)((WPTR) + 3 * 256);         \
        FMA8(w0, hv0.x, hv1.x, hv2.x, hv3.x);                         \
        FMA8(w1, hv0.y, hv1.y, hv2.y, hv3.y);                         \
        FMA8(w2, hv0.z, hv1.z, hv2.z, hv3.z);                         \
        FMA8(w3, hv0.w, hv1.w, hv2.w, hv3.w);                         \
    } while (0)

__global__ void __launch_bounds__(256, 1)
lstm_kernel(const int* __restrict__ x, const float* __restrict__ emb) {
    extern __shared__ char smem_raw[];
    Smem* s = reinterpret_cast<Smem*>(smem_raw);

    const int tid = threadIdx.x;
    const int j   = tid & 127;
    const int gp  = tid >> 7;
    const int b0  = blockIdx.x * BC;

    // Stage packed weights into smem.
    for (int i = tid; i < 2 * Esz * Hsz * 2; i += 256) s->wih[i] = g_wIhPack[i];
    for (int g = 0; g < 2; g++)
        for (int i = tid; i < KC * Hsz * 2; i += 256)
            s->whh[g * (KC * 256) + i] = g_wPack[g * (Hsz * 256) + i];
    // Token ids + state init.
    for (int bc = 0; bc < BC; bc++)
        for (int t = tid; t < Ssz; t += 256)
            s->tok[bc][t] = x[(b0 + bc) * Ssz + t];
    for (int i = tid; i < BC * Hsz; i += 256) {
        (&s->h[0][0])[i] = 0.0f;
        (&s->c[0][0])[i] = 0.0f;
    }
    __syncthreads();

    const int  bcp = tid / Esz;
    const int  eep = tid - bcp * Esz;
    const bool eTh = (tid < BC * Esz);
    if (eTh) s->e[0][bcp][eep] = emb[s->tok[bcp][0] * Esz + eep];

    const float bias0 = g_bias[(gp * Hsz + j) * 2 + 0];
    const float bias1 = g_bias[(gp * Hsz + j) * 2 + 1];
    const float* __restrict__ wHs = s->whh + gp * (KC * 256) + j * 2;              // k in [0,KC)
    const float* __restrict__ wHg = g_wPack + gp * (Hsz * 256) + KC * 256 + j * 2; // k in [KC,128)
    const float* __restrict__ wIs = s->wih + gp * (Esz * 256) + j * 2;
    __syncthreads();

    for (int st = 0; st < Ssz; st++) {
        const int buf = st & 1;

        // Prefetch next step's embedding row (latency hidden behind FMAs).
        float ev = 0.0f;
        const bool doE = eTh && (st + 1 < Ssz);
        if (doE) ev = emb[s->tok[bcp][st + 1] * Esz + eep];

        float a00 = bias0, a01 = bias0, a02 = bias0, a03 = bias0;
        float a10 = bias1, a11 = bias1, a12 = bias1, a13 = bias1;

        // Recurrent GEMV: smem-cached k slices.
        #pragma unroll 11
        for (int k4 = 0; k4 < KC / 4; k4++)
            KBODY(wHs + k4 * 1024, k4);
        // Recurrent GEMV: L2-streamed k slices.
        #pragma unroll 7
        for (int k4 = KC / 4; k4 < Hsz / 4; k4++)
            KBODY(wHg + (k4 - KC / 4) * 1024, k4);
        // Input GEMV (fused embedding): e over E=48, weights in smem.
        #pragma unroll 12
        for (int e4 = 0; e4 < Esz / 4; e4++) {
            const float4 ev0 = *(const float4*)(&s->e[buf][0][e4 * 4]);
            const float4 ev1 = *(const float4*)(&s->e[buf][1][e4 * 4]);
            const float4 ev2 = *(const float4*)(&s->e[buf][2][e4 * 4]);
            const float4 ev3 = *(const float4*)(&s->e[buf][3][e4 * 4]);
            const float2 w0 = *(const float2*)(wIs + (e4 * 4 + 0) * 256);
            const float2 w1 = *(const float2*)(wIs + (e4 * 4 + 1) * 256);
            const float2 w2 = *(const float2*)(wIs + (e4 * 4 + 2) * 256);
            const float2 w3 = *(const float2*)(wIs + (e4 * 4 + 3) * 256);
            FMA8(w0, ev0.x, ev1.x, ev2.x, ev3.x);
            FMA8(w1, ev0.y, ev1.y, ev2.y, ev3.y);
            FMA8(w2, ev0.z, ev1.z, ev2.z, ev3.z);
            FMA8(w3, ev0.w, ev1.w, ev2.w, ev3.w);
        }

        // Publish pre-activations.
        s->gbuf[gp * 2 + 0][0][j] = a00; s->gbuf[gp * 2 + 0][1][j] = a01;
        s->gbuf[gp * 2 + 0][2][j] = a02; s->gbuf[gp * 2 + 0][3][j] = a03;
        s->gbuf[gp * 2 + 1][0][j] = a10; s->gbuf[gp * 2 + 1][1][j] = a11;
        s->gbuf[gp * 2 + 1][2][j] = a12; s->gbuf[gp * 2 + 1][3][j] = a13;
        __syncthreads();

        // Gate combine: each thread owns 2 (bc,j) cells for the whole run.
        #pragma unroll
        for (int r = 0; r < 2; r++) {
            const int idx = tid + r * 256;
            const int bc = idx >> 7, jj = idx & 127;
            const float iv = sigf(s->gbuf[0][bc][jj]);
            const float fv = sigf(s->gbuf[1][bc][jj]);
            const float gv = tanhf(s->gbuf[2][bc][jj]);
            const float ov = sigf(s->gbuf[3][bc][jj]);
            const float cv = fv * s->c[bc][jj] + iv * gv;
            s->c[bc][jj] = cv;
            s->h[bc][jj] = ov * tanhf(cv);
        }
        if (doE) s->e[buf ^ 1][bcp][eep] = ev;
        __syncthreads();
    }

    // Export final hidden state.
    for (int i = tid; i < BC * Hsz; i += 256)
        g_hfin[(b0 + (i >> 7)) * Hsz + (i & 127)] = s->h[i >> 7][i & 127];
}

// ---------------------------------------------------------------------------
// FC epilogue: out[b][n] = h_fin[b] . w_fc[n] + b_fc[n]
// block = 128 threads over n, 8 batch rows per block.
// ---------------------------------------------------------------------------
__global__ void fc_kernel(const float* __restrict__ b_fc, float* __restrict__ out) {
    __shared__ float hs[8][Hsz];
    const int tid = threadIdx.x;
    const int n   = blockIdx.x * 128 + tid;
    const int bb  = blockIdx.y * 8;
    for (int i = tid; i < 8 * Hsz; i += 128)
        hs[i >> 7][i & 127] = g_hfin[(bb + (i >> 7)) * Hsz + (i & 127)];
    __syncthreads();
    if (n >= NCLS) return;
    const float bv = b_fc[n];
    float acc[8];
    #pragma unroll
    for (int i = 0; i < 8; i++) acc[i] = bv;
    #pragma unroll 4
    for (int k = 0; k < Hsz; k++) {
        const float w = g_wfcT[k * NCLS + n];
        #pragma unroll
        for (int i = 0; i < 8; i++) acc[i] = fmaf(hs[i][k], w, acc[i]);
    }
    #pragma unroll
    for (int i = 0; i < 8; i++) out[(bb + i) * NCLS + n] = acc[i];
}

extern "C" void kernel_launch(void* const* d_in, const int* in_sizes, int n_in,
                              void* d_out, int out_size) {
    const int*   x    = (const int*)  d_in[0];
    const float* emb  = (const float*)d_in[1];
    const float* w_ih = (const float*)d_in[2];
    const float* w_hh = (const float*)d_in[3];
    const float* b_ih = (const float*)d_in[4];
    const float* b_hh = (const float*)d_in[5];
    const float* w_fc = (const float*)d_in[6];
    const float* b_fc = (const float*)d_in[7];
    float* out = (float*)d_out;

    static bool attr_set = false;
    if (!attr_set) {
        cudaFuncSetAttribute(lstm_kernel, cudaFuncAttributeMaxDynamicSharedMemorySize,
                             (int)sizeof(Smem));
        attr_set = true;
    }

    prep_kernel<<<1000, 256>>>(w_ih, w_hh, b_ih, b_hh, w_fc);
    lstm_kernel<<<Bsz / BC, 256, sizeof(Smem)>>>(x, emb);
    fc_kernel<<<dim3((NCLS + 127) / 128, Bsz / 8), 128>>>(b_fc, out);
}